// round 1
// baseline (speedup 1.0000x reference)
#include <cuda_runtime.h>

#define BATCH 16384
#define IN_DIM 768
#define LATENT 12288
#define KSEL 32

// ---------------- scratch (static device allocs; no cudaMalloc) ----------------
__device__ float g_z[(size_t)BATCH * LATENT];      // encoder pre-activations (805 MB)
__device__ float g_decT[(size_t)LATENT * IN_DIM];  // dec_w transposed [LATENT][IN_DIM]
__device__ float g_sv[(size_t)BATCH * KSEL];       // compacted sparse values (z - thresh)
__device__ int   g_si[(size_t)BATCH * KSEL];       // compacted sparse indices
__device__ int   g_nnz[BATCH];

// ---------------- 1) transpose dec_w [IN_DIM][LATENT] -> g_decT [LATENT][IN_DIM] ----
__global__ void transpose_dec_kernel(const float* __restrict__ dec_w) {
    __shared__ float tile[32][33];
    int lb = blockIdx.x * 32;  // latent base
    int ib = blockIdx.y * 32;  // in_dim base
    int tx = threadIdx.x;      // 0..31
    int ty = threadIdx.y;      // 0..7
#pragma unroll
    for (int j = 0; j < 4; j++) {
        int i = ib + ty + j * 8;
        tile[ty + j * 8][tx] = dec_w[(size_t)i * LATENT + lb + tx];
    }
    __syncthreads();
#pragma unroll
    for (int j = 0; j < 4; j++) {
        int l = lb + ty + j * 8;
        g_decT[(size_t)l * IN_DIM + ib + tx] = tile[tx][ty + j * 8];
    }
}

// ---------------- 2) encoder GEMM: g_z[b][l] = sum_i x[b][i]*enc_w[l][i] + enc_b[l] --
// Classic 128x128x8 fp32 tile, 256 threads, 8x8 per thread.
#define BM 128
#define BN 128
#define BK 8
__global__ void __launch_bounds__(256) encoder_gemm_kernel(
    const float* __restrict__ A,    // x      [BATCH][IN_DIM]
    const float* __restrict__ Bw,   // enc_w  [LATENT][IN_DIM]
    const float* __restrict__ bias) // enc_b  [LATENT]
{
    __shared__ __align__(16) float As[BK][BM];
    __shared__ __align__(16) float Bs[BK][BN];

    int bm = blockIdx.y * BM;
    int bn = blockIdx.x * BN;
    int tid = threadIdx.x;
    int tx = tid % 16;  // col group
    int ty = tid / 16;  // row group

    // global-load mapping: 256 threads cover 128 rows x 8 k-cols via float4
    int lr = tid >> 1;          // 0..127
    int lc = (tid & 1) * 4;     // 0 or 4
    const float* Aptr = A  + (size_t)(bm + lr) * IN_DIM + lc;
    const float* Bptr = Bw + (size_t)(bn + lr) * IN_DIM + lc;

    float acc[8][8];
#pragma unroll
    for (int i = 0; i < 8; i++)
#pragma unroll
        for (int j = 0; j < 8; j++) acc[i][j] = 0.0f;

    for (int k0 = 0; k0 < IN_DIM; k0 += BK) {
        float4 av = *(const float4*)(Aptr + k0);
        float4 bv = *(const float4*)(Bptr + k0);
        As[lc + 0][lr] = av.x; As[lc + 1][lr] = av.y;
        As[lc + 2][lr] = av.z; As[lc + 3][lr] = av.w;
        Bs[lc + 0][lr] = bv.x; Bs[lc + 1][lr] = bv.y;
        Bs[lc + 2][lr] = bv.z; Bs[lc + 3][lr] = bv.w;
        __syncthreads();

#pragma unroll
        for (int k = 0; k < BK; k++) {
            float4 a0 = *(const float4*)&As[k][ty * 8];
            float4 a1 = *(const float4*)&As[k][ty * 8 + 4];
            float4 b0 = *(const float4*)&Bs[k][tx * 8];
            float4 b1 = *(const float4*)&Bs[k][tx * 8 + 4];
            float a[8] = {a0.x, a0.y, a0.z, a0.w, a1.x, a1.y, a1.z, a1.w};
            float b[8] = {b0.x, b0.y, b0.z, b0.w, b1.x, b1.y, b1.z, b1.w};
#pragma unroll
            for (int i = 0; i < 8; i++)
#pragma unroll
                for (int j = 0; j < 8; j++) acc[i][j] += a[i] * b[j];
        }
        __syncthreads();
    }

    // epilogue: + bias, write g_z as float4
    float bb[8];
#pragma unroll
    for (int j = 0; j < 8; j++) bb[j] = bias[bn + tx * 8 + j];
#pragma unroll
    for (int i = 0; i < 8; i++) {
        size_t ro = (size_t)(bm + ty * 8 + i) * LATENT + bn + tx * 8;
        float4 o0 = make_float4(acc[i][0] + bb[0], acc[i][1] + bb[1],
                                acc[i][2] + bb[2], acc[i][3] + bb[3]);
        float4 o1 = make_float4(acc[i][4] + bb[4], acc[i][5] + bb[5],
                                acc[i][6] + bb[6], acc[i][7] + bb[7]);
        *(float4*)&g_z[ro]     = o0;
        *(float4*)&g_z[ro + 4] = o1;
    }
}

// ---------------- 3) per-row exact top-k (radix select) + z_sparse write + compact --
// key transform: monotone map float -> uint32 (ascending)
__device__ __forceinline__ unsigned f2k(unsigned u) {
    return u ^ ((u & 0x80000000u) ? 0xFFFFFFFFu : 0x80000000u);
}
__device__ __forceinline__ float k2f(unsigned k) {
    unsigned u = (k & 0x80000000u) ? (k ^ 0x80000000u) : ~k;
    return __uint_as_float(u);
}

__global__ void __launch_bounds__(256) topk_kernel(float* __restrict__ zs_out) {
    extern __shared__ unsigned smem[];
    unsigned* keys = smem;           // LATENT keys
    unsigned* hist = smem + LATENT;  // 256 bins
    __shared__ int s_bin, s_need, s_cnt;

    int row = blockIdx.x;
    int tid = threadIdx.x;
    const float* zr = g_z + (size_t)row * LATENT;

    for (int i = tid; i < LATENT; i += 256)
        keys[i] = f2k(__float_as_uint(zr[i]));
    if (tid == 0) { s_need = KSEL; s_cnt = 0; }

    unsigned prefix = 0, prefmask = 0;
#pragma unroll
    for (int shift = 24; shift >= 0; shift -= 8) {
        hist[tid] = 0;
        __syncthreads();
        for (int i = tid; i < LATENT; i += 256) {
            unsigned k = keys[i];
            if ((k & prefmask) == prefix)
                atomicAdd(&hist[(k >> shift) & 0xFFu], 1u);
        }
        __syncthreads();
        if (tid == 0) {
            int need = s_need;
            int b = 255;
            for (; b > 0; b--) {
                int c = (int)hist[b];
                if (c >= need) break;
                need -= c;
            }
            s_bin = b;
            s_need = need;
        }
        __syncthreads();
        prefix |= ((unsigned)s_bin) << shift;
        prefmask |= 0xFFu << shift;
    }

    // prefix == key of the exact K-th largest value
    float thresh = k2f(prefix);
    float* outr = zs_out + (size_t)row * LATENT;
    for (int i = tid; i < LATENT; i += 256) {
        unsigned k = keys[i];
        float v = k2f(k);
        float d = v - thresh;
        outr[i] = d > 0.0f ? d : 0.0f;
        if (k > prefix) {  // strictly above threshold: at most KSEL-1 entries
            int p = atomicAdd(&s_cnt, 1);
            g_sv[(size_t)row * KSEL + p] = d;
            g_si[(size_t)row * KSEL + p] = i;
        }
    }
    __syncthreads();
    if (tid == 0) g_nnz[row] = s_cnt;
}

// ---------------- 4) sparse decoder: x_recon[b] = sum_j val_j * decT[idx_j] + dec_b --
__global__ void __launch_bounds__(256) decoder_kernel(
    const float* __restrict__ dec_b, float* __restrict__ xr)
{
    __shared__ float sval[KSEL];
    __shared__ int   sidx[KSEL];
    __shared__ int   snnz;
    int row = blockIdx.x;
    int tid = threadIdx.x;
    if (tid == 0) snnz = g_nnz[row];
    if (tid < KSEL) {
        sval[tid] = g_sv[(size_t)row * KSEL + tid];
        sidx[tid] = g_si[(size_t)row * KSEL + tid];
    }
    __syncthreads();

    int n = snnz;
    int c0 = tid, c1 = tid + 256, c2 = tid + 512;
    float acc0 = 0.f, acc1 = 0.f, acc2 = 0.f;
    for (int j = 0; j < n; j++) {
        float v = sval[j];
        const float* wrow = g_decT + (size_t)sidx[j] * IN_DIM;
        acc0 += v * wrow[c0];
        acc1 += v * wrow[c1];
        acc2 += v * wrow[c2];
    }
    float* o = xr + (size_t)row * IN_DIM;
    o[c0] = acc0 + dec_b[c0];
    o[c1] = acc1 + dec_b[c1];
    o[c2] = acc2 + dec_b[c2];
}

// ---------------- launch ----------------
extern "C" void kernel_launch(void* const* d_in, const int* in_sizes, int n_in,
                              void* d_out, int out_size) {
    const float* x     = (const float*)d_in[0];
    const float* enc_w = (const float*)d_in[1];
    const float* enc_b = (const float*)d_in[2];
    const float* dec_w = (const float*)d_in[3];
    const float* dec_b = (const float*)d_in[4];
    // d_in[5] = k (always 32 for this problem; compile-time constant)

    float* out      = (float*)d_out;
    float* x_recon  = out;                                // [BATCH][IN_DIM]
    float* z_sparse = out + (size_t)BATCH * IN_DIM;       // [BATCH][LATENT]

    transpose_dec_kernel<<<dim3(LATENT / 32, IN_DIM / 32), dim3(32, 8)>>>(dec_w);

    encoder_gemm_kernel<<<dim3(LATENT / BN, BATCH / BM), 256>>>(x, enc_w, enc_b);

    const int topk_smem = LATENT * 4 + 256 * 4;  // 50176 bytes
    cudaFuncSetAttribute(topk_kernel, cudaFuncAttributeMaxDynamicSharedMemorySize, topk_smem);
    topk_kernel<<<BATCH, 256, topk_smem>>>(z_sparse);

    decoder_kernel<<<BATCH, 256>>>(dec_b, x_recon);
}

// round 3
// speedup vs baseline: 3.7640x; 3.7640x over previous
#include <cuda_runtime.h>
#include <cuda_bf16.h>
#include <cstdint>

#define BATCH 16384
#define IN_DIM 768
#define LATENT 12288
#define KSEL 32
#define MARGIN 0.05f
#define MAXCAND 128

// ---------------- scratch (static device arrays; no cudaMalloc) ----------------
__device__ float g_z[(size_t)BATCH * LATENT];      // approx encoder pre-activations
__device__ float g_decT[(size_t)LATENT * IN_DIM];  // dec_w transposed
__device__ float g_sv[(size_t)BATCH * KSEL];
__device__ int   g_si[(size_t)BATCH * KSEL];
__device__ int   g_nnz[BATCH];
__device__ __nv_bfloat16 g_xb[(size_t)BATCH * IN_DIM];
__device__ __nv_bfloat16 g_wb[(size_t)LATENT * IN_DIM];

// ---------------- helpers ----------------
__device__ __forceinline__ uint32_t s2u(const void* p) {
    return (uint32_t)__cvta_generic_to_shared(p);
}
__device__ __forceinline__ void cp16(uint32_t d, const void* s) {
    asm volatile("cp.async.cg.shared.global [%0], [%1], 16;" :: "r"(d), "l"(s));
}
__device__ __forceinline__ void ldsm4(uint32_t* r, uint32_t addr) {
    asm volatile("ldmatrix.sync.aligned.m8n8.x4.shared.b16 {%0,%1,%2,%3}, [%4];"
        : "=r"(r[0]), "=r"(r[1]), "=r"(r[2]), "=r"(r[3]) : "r"(addr));
}
__device__ __forceinline__ void mma16816(float* c, const uint32_t* a, const uint32_t* b) {
    asm volatile("mma.sync.aligned.m16n8k16.row.col.f32.bf16.bf16.f32 "
        "{%0,%1,%2,%3}, {%4,%5,%6,%7}, {%8,%9}, {%0,%1,%2,%3};"
        : "+f"(c[0]), "+f"(c[1]), "+f"(c[2]), "+f"(c[3])
        : "r"(a[0]), "r"(a[1]), "r"(a[2]), "r"(a[3]), "r"(b[0]), "r"(b[1]));
}

// ---------------- 0) fp32 -> bf16 convert ----------------
__global__ void convert_bf16_kernel(const float* __restrict__ src,
                                    __nv_bfloat16* __restrict__ dst, int n4) {
    int i = blockIdx.x * blockDim.x + threadIdx.x;
    if (i >= n4) return;
    float4 v = ((const float4*)src)[i];
    __nv_bfloat16 h[4] = {__float2bfloat16(v.x), __float2bfloat16(v.y),
                          __float2bfloat16(v.z), __float2bfloat16(v.w)};
    ((uint2*)dst)[i] = *(uint2*)h;
}

// ---------------- 1) transpose dec_w ----------------
__global__ void transpose_dec_kernel(const float* __restrict__ dec_w) {
    __shared__ float tile[32][33];
    int lb = blockIdx.x * 32;
    int ib = blockIdx.y * 32;
    int tx = threadIdx.x;
    int ty = threadIdx.y;
#pragma unroll
    for (int j = 0; j < 4; j++)
        tile[ty + j * 8][tx] = dec_w[(size_t)(ib + ty + j * 8) * LATENT + lb + tx];
    __syncthreads();
#pragma unroll
    for (int j = 0; j < 4; j++)
        g_decT[(size_t)(lb + ty + j * 8) * IN_DIM + ib + tx] = tile[tx][ty + j * 8];
}

// ---------------- 2) encoder bf16 HMMA GEMM: 128x128 CTA, 64x32 warp, k-chunk 64 ----
#define BM 128
#define BN 128
#define STAGE_BYTES 32768   // A 16K + B 16K
#define N_CH 12             // 768 / 64

__global__ void __launch_bounds__(256, 2) encoder_hmma_kernel(const float* __restrict__ bias) {
    extern __shared__ char smem[];
    __shared__ float sbias[BN];
    uint32_t sb = s2u(smem);
    int tid = threadIdx.x, lane = tid & 31, wid = tid >> 5;
    int wm = (wid & 1) * 64, wn = (wid >> 1) * 32;
    int bm = blockIdx.y * BM, bn = blockIdx.x * BN;
    if (tid < BN) sbias[tid] = bias[bn + tid];

    const __nv_bfloat16* Ag = g_xb + (size_t)bm * IN_DIM;
    const __nv_bfloat16* Bg = g_wb + (size_t)bn * IN_DIM;

    auto load_stage = [&](int st, int ch) {
        uint32_t a0 = sb + st * STAGE_BYTES;
        uint32_t b0 = a0 + 16384;
        int k0 = ch * 64;
#pragma unroll
        for (int it = 0; it < 4; it++) {
            int idx = tid + it * 256;
            int r = idx >> 3, c = idx & 7;
            uint32_t off = (uint32_t)(r * 128 + (((c ^ (r & 7))) << 4));
            const __nv_bfloat16* as = Ag + (size_t)r * IN_DIM + k0 + c * 8;
            const __nv_bfloat16* bs = Bg + (size_t)r * IN_DIM + k0 + c * 8;
            cp16(a0 + off, as);
            cp16(b0 + off, bs);
        }
        asm volatile("cp.async.commit_group;");
    };

    // per-thread ldmatrix row bases
    uint32_t a_row[4], b_row[2];
    uint32_t a_x[4], b_x[2];
#pragma unroll
    for (int mt = 0; mt < 4; mt++) {
        int r = wm + mt * 16 + (lane & 15);
        a_row[mt] = (uint32_t)(r * 128);
        a_x[mt] = (uint32_t)((r & 7) << 4);
    }
#pragma unroll
    for (int pt = 0; pt < 2; pt++) {
        int r = wn + pt * 16 + (lane & 15);
        b_row[pt] = (uint32_t)(r * 128);
        b_x[pt] = (uint32_t)((r & 7) << 4);
    }
    int khalf = lane >> 4;

    float acc[4][4][4];
#pragma unroll
    for (int i = 0; i < 4; i++)
#pragma unroll
        for (int j = 0; j < 4; j++)
#pragma unroll
            for (int q = 0; q < 4; q++) acc[i][j][q] = 0.0f;

    load_stage(0, 0);
    load_stage(1, 1);

    for (int ch = 0; ch < N_CH; ch++) {
        int st = ch % 3;
        asm volatile("cp.async.wait_group 1;");
        __syncthreads();
        if (ch + 2 < N_CH) load_stage((ch + 2) % 3, ch + 2);
        else asm volatile("cp.async.commit_group;");

        uint32_t abase = sb + st * STAGE_BYTES;
        uint32_t bbase = abase + 16384;
#pragma unroll
        for (int ks = 0; ks < 4; ks++) {
            uint32_t chunk = (uint32_t)(ks * 2 + khalf) << 4;
            uint32_t a[4][4], b[4][2];
#pragma unroll
            for (int mt = 0; mt < 4; mt++)
                ldsm4(a[mt], abase + a_row[mt] + (chunk ^ a_x[mt]));
#pragma unroll
            for (int pt = 0; pt < 2; pt++) {
                uint32_t r[4];
                ldsm4(r, bbase + b_row[pt] + (chunk ^ b_x[pt]));
                b[2 * pt][0] = r[0]; b[2 * pt + 1][0] = r[1];
                b[2 * pt][1] = r[2]; b[2 * pt + 1][1] = r[3];
            }
#pragma unroll
            for (int mt = 0; mt < 4; mt++)
#pragma unroll
                for (int nt = 0; nt < 4; nt++)
                    mma16816(acc[mt][nt], a[mt], b[nt]);
        }
    }

    // epilogue: + bias, write g_z
#pragma unroll
    for (int mt = 0; mt < 4; mt++) {
        int m0 = bm + wm + mt * 16 + (lane >> 2);
#pragma unroll
        for (int nt = 0; nt < 4; nt++) {
            float* c = acc[mt][nt];
            int nl = wn + nt * 8 + (lane & 3) * 2;
            size_t o = (size_t)m0 * LATENT + bn + nl;
            float b0 = sbias[nl], b1 = sbias[nl + 1];
            float2 v0 = make_float2(c[0] + b0, c[1] + b1);
            float2 v1 = make_float2(c[2] + b0, c[3] + b1);
            *(float2*)&g_z[o] = v0;
            *(float2*)&g_z[o + (size_t)8 * LATENT] = v1;
        }
    }
}

// ---------------- 3) top-k: radix select on approx + exact fp32 rescue ----------------
__device__ __forceinline__ unsigned f2k(unsigned u) {
    return u ^ ((u & 0x80000000u) ? 0xFFFFFFFFu : 0x80000000u);
}
__device__ __forceinline__ float k2f(unsigned k) {
    unsigned u = (k & 0x80000000u) ? (k ^ 0x80000000u) : ~k;
    return __uint_as_float(u);
}

__global__ void __launch_bounds__(256) topk_kernel(
    const float* __restrict__ x, const float* __restrict__ enc_w,
    const float* __restrict__ enc_b, float* __restrict__ zs_out)
{
    extern __shared__ unsigned tsm[];
    unsigned* keys = tsm;                       // LATENT
    unsigned* hist = tsm + LATENT;              // 256
    float* xrow = (float*)(hist + 256);         // IN_DIM
    int* cidx = (int*)(xrow + IN_DIM);          // MAXCAND
    float* cval = (float*)(cidx + MAXCAND);     // MAXCAND
    __shared__ int s_bin, s_need, s_cnt, s_nnz;
    __shared__ unsigned s_tkey;

    int row = blockIdx.x;
    int tid = threadIdx.x;
    const float* zr = g_z + (size_t)row * LATENT;

    for (int i = tid; i < LATENT; i += 256)
        keys[i] = f2k(__float_as_uint(zr[i]));
    for (int i = tid; i < IN_DIM; i += 256)
        xrow[i] = x[(size_t)row * IN_DIM + i];
    if (tid == 0) { s_need = KSEL; s_cnt = 0; s_nnz = 0; s_tkey = 0xFFFFFFFFu; }

    // radix select: key of approx 32nd-largest
    unsigned prefix = 0, pm = 0;
#pragma unroll
    for (int shift = 24; shift >= 0; shift -= 8) {
        hist[tid] = 0;
        __syncthreads();
        for (int i = tid; i < LATENT; i += 256) {
            unsigned k = keys[i];
            if ((k & pm) == prefix)
                atomicAdd(&hist[(k >> shift) & 0xFFu], 1u);
        }
        __syncthreads();
        if (tid == 0) {
            int need = s_need;
            int b = 255;
            for (; b > 0; b--) {
                int c = (int)hist[b];
                if (c >= need) break;
                need -= c;
            }
            s_bin = b;
            s_need = need;
        }
        __syncthreads();
        prefix |= ((unsigned)s_bin) << shift;
        pm |= 0xFFu << shift;
    }

    // collect candidates above margin cut
    float cut = k2f(prefix) - MARGIN;
    for (int i = tid; i < LATENT; i += 256) {
        if (k2f(keys[i]) > cut) {
            int p = atomicAdd(&s_cnt, 1);
            if (p < MAXCAND) cidx[p] = i;
        }
    }
    __syncthreads();
    int ncand = min(s_cnt, MAXCAND);

    // exact fp32 recompute of candidates
    int wid = tid >> 5, lane = tid & 31;
    for (int c = wid; c < ncand; c += 8) {
        const float* wr = enc_w + (size_t)cidx[c] * IN_DIM;
        float p = 0.0f;
        for (int j = lane; j < IN_DIM; j += 32) p += xrow[j] * wr[j];
#pragma unroll
        for (int o = 16; o; o >>= 1) p += __shfl_xor_sync(0xFFFFFFFFu, p, o);
        if (lane == 0) cval[c] = p + enc_b[cidx[c]];
    }
    __syncthreads();

    // exact 32nd largest among candidates: min v with count_greater(v) <= 31
    if (tid < ncand) {
        float v = cval[tid];
        int cg = 0;
        for (int j = 0; j < ncand; j++) cg += (cval[j] > v) ? 1 : 0;
        if (cg <= KSEL - 1) atomicMin(&s_tkey, f2k(__float_as_uint(v)));
    }
    __syncthreads();
    float thresh = k2f(s_tkey);

    // write z_sparse: zero row, then exact sparse entries
    float* outr = zs_out + (size_t)row * LATENT;
    for (int i = tid; i < LATENT; i += 256) outr[i] = 0.0f;
    __syncthreads();
    if (tid < ncand) {
        float d = cval[tid] - thresh;
        if (d > 0.0f) {
            outr[cidx[tid]] = d;
            int p = atomicAdd(&s_nnz, 1);
            g_sv[(size_t)row * KSEL + p] = d;
            g_si[(size_t)row * KSEL + p] = cidx[tid];
        }
    }
    __syncthreads();
    if (tid == 0) g_nnz[row] = s_nnz;
}

// ---------------- 4) sparse decoder ----------------
__global__ void __launch_bounds__(256) decoder_kernel(
    const float* __restrict__ dec_b, float* __restrict__ xr)
{
    __shared__ float sval[KSEL];
    __shared__ int   sidx[KSEL];
    __shared__ int   snnz;
    int row = blockIdx.x;
    int tid = threadIdx.x;
    if (tid == 0) snnz = g_nnz[row];
    if (tid < KSEL) {
        sval[tid] = g_sv[(size_t)row * KSEL + tid];
        sidx[tid] = g_si[(size_t)row * KSEL + tid];
    }
    __syncthreads();

    int n = snnz;
    int c0 = tid, c1 = tid + 256, c2 = tid + 512;
    float acc0 = 0.f, acc1 = 0.f, acc2 = 0.f;
    for (int j = 0; j < n; j++) {
        float v = sval[j];
        const float* wrow = g_decT + (size_t)sidx[j] * IN_DIM;
        acc0 += v * wrow[c0];
        acc1 += v * wrow[c1];
        acc2 += v * wrow[c2];
    }
    float* o = xr + (size_t)row * IN_DIM;
    o[c0] = acc0 + dec_b[c0];
    o[c1] = acc1 + dec_b[c1];
    o[c2] = acc2 + dec_b[c2];
}

// ---------------- launch ----------------
extern "C" void kernel_launch(void* const* d_in, const int* in_sizes, int n_in,
                              void* d_out, int out_size) {
    const float* x     = (const float*)d_in[0];
    const float* enc_w = (const float*)d_in[1];
    const float* enc_b = (const float*)d_in[2];
    const float* dec_w = (const float*)d_in[3];
    const float* dec_b = (const float*)d_in[4];

    float* out      = (float*)d_out;
    float* x_recon  = out;
    float* z_sparse = out + (size_t)BATCH * IN_DIM;

    __nv_bfloat16 *xb, *wb;
    cudaGetSymbolAddress((void**)&xb, g_xb);
    cudaGetSymbolAddress((void**)&wb, g_wb);

    int nx4 = BATCH * IN_DIM / 4;
    int nw4 = LATENT * IN_DIM / 4;
    convert_bf16_kernel<<<(nx4 + 255) / 256, 256>>>(x, xb, nx4);
    convert_bf16_kernel<<<(nw4 + 255) / 256, 256>>>(enc_w, wb, nw4);

    transpose_dec_kernel<<<dim3(LATENT / 32, IN_DIM / 32), dim3(32, 8)>>>(dec_w);

    const int gemm_smem = 3 * STAGE_BYTES;  // 98304
    cudaFuncSetAttribute(encoder_hmma_kernel,
                         cudaFuncAttributeMaxDynamicSharedMemorySize, gemm_smem);
    encoder_hmma_kernel<<<dim3(LATENT / BN, BATCH / BM), 256, gemm_smem>>>(enc_b);

    const int topk_smem = LATENT * 4 + 256 * 4 + IN_DIM * 4 + MAXCAND * 8;
    cudaFuncSetAttribute(topk_kernel, cudaFuncAttributeMaxDynamicSharedMemorySize, topk_smem);
    topk_kernel<<<BATCH, 256, topk_smem>>>(x, enc_w, enc_b, z_sparse);

    decoder_kernel<<<BATCH, 256>>>(dec_b, x_recon);
}

// round 4
// speedup vs baseline: 4.8756x; 1.2953x over previous
#include <cuda_runtime.h>
#include <cuda_bf16.h>
#include <cstdint>

#define BATCH 16384
#define IN_DIM 768
#define LATENT 12288
#define KSEL 32
#define MARGIN 0.06f
#define MAXCAND 128

// ---------------- scratch (static device arrays; no cudaMalloc) ----------------
__device__ __nv_bfloat16 g_zb[(size_t)BATCH * LATENT];  // approx z in bf16
__device__ float g_decT[(size_t)LATENT * IN_DIM];
__device__ float g_sv[(size_t)BATCH * KSEL];
__device__ int   g_si[(size_t)BATCH * KSEL];
__device__ int   g_nnz[BATCH];
__device__ __nv_bfloat16 g_xb[(size_t)BATCH * IN_DIM];
__device__ __nv_bfloat16 g_wb[(size_t)LATENT * IN_DIM];

// ---------------- helpers ----------------
__device__ __forceinline__ uint32_t s2u(const void* p) {
    return (uint32_t)__cvta_generic_to_shared(p);
}
__device__ __forceinline__ void cp16(uint32_t d, const void* s) {
    asm volatile("cp.async.cg.shared.global [%0], [%1], 16;" :: "r"(d), "l"(s));
}
__device__ __forceinline__ void ldsm4(uint32_t* r, uint32_t addr) {
    asm volatile("ldmatrix.sync.aligned.m8n8.x4.shared.b16 {%0,%1,%2,%3}, [%4];"
        : "=r"(r[0]), "=r"(r[1]), "=r"(r[2]), "=r"(r[3]) : "r"(addr));
}
__device__ __forceinline__ void mma16816(float* c, const uint32_t* a, const uint32_t* b) {
    asm volatile("mma.sync.aligned.m16n8k16.row.col.f32.bf16.bf16.f32 "
        "{%0,%1,%2,%3}, {%4,%5,%6,%7}, {%8,%9}, {%0,%1,%2,%3};"
        : "+f"(c[0]), "+f"(c[1]), "+f"(c[2]), "+f"(c[3])
        : "r"(a[0]), "r"(a[1]), "r"(a[2]), "r"(a[3]), "r"(b[0]), "r"(b[1]));
}

// ---------------- 0) fp32 -> bf16 convert ----------------
__global__ void convert_bf16_kernel(const float* __restrict__ src,
                                    __nv_bfloat16* __restrict__ dst, int n4) {
    int i = blockIdx.x * blockDim.x + threadIdx.x;
    if (i >= n4) return;
    float4 v = ((const float4*)src)[i];
    __nv_bfloat16 h[4] = {__float2bfloat16(v.x), __float2bfloat16(v.y),
                          __float2bfloat16(v.z), __float2bfloat16(v.w)};
    ((uint2*)dst)[i] = *(uint2*)h;
}

// ---------------- 1) transpose dec_w ----------------
__global__ void transpose_dec_kernel(const float* __restrict__ dec_w) {
    __shared__ float tile[32][33];
    int lb = blockIdx.x * 32;
    int ib = blockIdx.y * 32;
    int tx = threadIdx.x;
    int ty = threadIdx.y;
#pragma unroll
    for (int j = 0; j < 4; j++)
        tile[ty + j * 8][tx] = dec_w[(size_t)(ib + ty + j * 8) * LATENT + lb + tx];
    __syncthreads();
#pragma unroll
    for (int j = 0; j < 4; j++)
        g_decT[(size_t)(lb + ty + j * 8) * IN_DIM + ib + tx] = tile[tx][ty + j * 8];
}

// ---------------- 2) encoder bf16 HMMA GEMM: 128x128 CTA, 64x32 warp, k-chunk 64 ----
#define BM 128
#define BN 128
#define STAGE_BYTES 32768   // A 16K + B 16K
#define N_CH 12             // 768 / 64

__global__ void __launch_bounds__(256, 2) encoder_hmma_kernel(const float* __restrict__ bias) {
    extern __shared__ char smem[];
    __shared__ float sbias[BN];
    uint32_t sb = s2u(smem);
    int tid = threadIdx.x, lane = tid & 31, wid = tid >> 5;
    int wm = (wid & 1) * 64, wn = (wid >> 1) * 32;
    int bm = blockIdx.y * BM, bn = blockIdx.x * BN;
    if (tid < BN) sbias[tid] = bias[bn + tid];

    const __nv_bfloat16* Ag = g_xb + (size_t)bm * IN_DIM;
    const __nv_bfloat16* Bg = g_wb + (size_t)bn * IN_DIM;

    auto load_stage = [&](int st, int ch) {
        uint32_t a0 = sb + st * STAGE_BYTES;
        uint32_t b0 = a0 + 16384;
        int k0 = ch * 64;
#pragma unroll
        for (int it = 0; it < 4; it++) {
            int idx = tid + it * 256;
            int r = idx >> 3, c = idx & 7;
            uint32_t off = (uint32_t)(r * 128 + (((c ^ (r & 7))) << 4));
            const __nv_bfloat16* as = Ag + (size_t)r * IN_DIM + k0 + c * 8;
            const __nv_bfloat16* bs = Bg + (size_t)r * IN_DIM + k0 + c * 8;
            cp16(a0 + off, as);
            cp16(b0 + off, bs);
        }
        asm volatile("cp.async.commit_group;");
    };

    uint32_t a_row[4], b_row[2];
    uint32_t a_x[4], b_x[2];
#pragma unroll
    for (int mt = 0; mt < 4; mt++) {
        int r = wm + mt * 16 + (lane & 15);
        a_row[mt] = (uint32_t)(r * 128);
        a_x[mt] = (uint32_t)((r & 7) << 4);
    }
#pragma unroll
    for (int pt = 0; pt < 2; pt++) {
        int r = wn + pt * 16 + (lane & 15);
        b_row[pt] = (uint32_t)(r * 128);
        b_x[pt] = (uint32_t)((r & 7) << 4);
    }
    int khalf = lane >> 4;

    float acc[4][4][4];
#pragma unroll
    for (int i = 0; i < 4; i++)
#pragma unroll
        for (int j = 0; j < 4; j++)
#pragma unroll
            for (int q = 0; q < 4; q++) acc[i][j][q] = 0.0f;

    load_stage(0, 0);
    load_stage(1, 1);

    for (int ch = 0; ch < N_CH; ch++) {
        int st = ch % 3;
        asm volatile("cp.async.wait_group 1;");
        __syncthreads();
        if (ch + 2 < N_CH) load_stage((ch + 2) % 3, ch + 2);
        else asm volatile("cp.async.commit_group;");

        uint32_t abase = sb + st * STAGE_BYTES;
        uint32_t bbase = abase + 16384;
#pragma unroll
        for (int ks = 0; ks < 4; ks++) {
            uint32_t chunk = (uint32_t)(ks * 2 + khalf) << 4;
            uint32_t a[4][4], b[4][2];
#pragma unroll
            for (int mt = 0; mt < 4; mt++)
                ldsm4(a[mt], abase + a_row[mt] + (chunk ^ a_x[mt]));
#pragma unroll
            for (int pt = 0; pt < 2; pt++) {
                uint32_t r[4];
                ldsm4(r, bbase + b_row[pt] + (chunk ^ b_x[pt]));
                b[2 * pt][0] = r[0]; b[2 * pt + 1][0] = r[1];
                b[2 * pt][1] = r[2]; b[2 * pt + 1][1] = r[3];
            }
#pragma unroll
            for (int mt = 0; mt < 4; mt++)
#pragma unroll
                for (int nt = 0; nt < 4; nt++)
                    mma16816(acc[mt][nt], a[mt], b[nt]);
        }
    }

    // epilogue: + bias, convert to bf16, write g_zb (4B packed stores)
#pragma unroll
    for (int mt = 0; mt < 4; mt++) {
        int m0 = bm + wm + mt * 16 + (lane >> 2);
#pragma unroll
        for (int nt = 0; nt < 4; nt++) {
            float* c = acc[mt][nt];
            int nl = wn + nt * 8 + (lane & 3) * 2;
            size_t o = (size_t)m0 * LATENT + bn + nl;
            float b0 = sbias[nl], b1 = sbias[nl + 1];
            __nv_bfloat162 v0 = __floats2bfloat162_rn(c[0] + b0, c[1] + b1);
            __nv_bfloat162 v1 = __floats2bfloat162_rn(c[2] + b0, c[3] + b1);
            *(__nv_bfloat162*)&g_zb[o] = v0;
            *(__nv_bfloat162*)&g_zb[o + (size_t)8 * LATENT] = v1;
        }
    }
}

// ---------------- 3) top-k: 16-bit radix select on bf16 approx + exact fp32 rescue --
__device__ __forceinline__ unsigned f2k32(unsigned u) {
    return u ^ ((u & 0x80000000u) ? 0xFFFFFFFFu : 0x80000000u);
}
__device__ __forceinline__ float k2f32(unsigned k) {
    unsigned u = (k & 0x80000000u) ? (k ^ 0x80000000u) : ~k;
    return __uint_as_float(u);
}
__device__ __forceinline__ uint32_t f2k16(uint32_t u) {  // u: bf16 bits in low 16
    return (u ^ ((u & 0x8000u) ? 0xFFFFu : 0x8000u)) & 0xFFFFu;
}
__device__ __forceinline__ float k2f16(uint32_t k) {
    uint32_t u = (k & 0x8000u) ? (k ^ 0x8000u) : (~k & 0xFFFFu);
    return __uint_as_float(u << 16);
}

__global__ void __launch_bounds__(256) topk_kernel(
    const float* __restrict__ x, const float* __restrict__ enc_w,
    const float* __restrict__ enc_b, float* __restrict__ zs_out)
{
    extern __shared__ unsigned tsm[];
    uint16_t* keys = (uint16_t*)tsm;                 // LATENT u16 (24 KB)
    unsigned* hist = (unsigned*)(keys + LATENT);     // 256
    float* xrow = (float*)(hist + 256);              // IN_DIM
    int* cidx = (int*)(xrow + IN_DIM);               // MAXCAND
    float* cval = (float*)(cidx + MAXCAND);          // MAXCAND
    __shared__ int s_bin, s_need, s_cnt, s_nnz;
    __shared__ unsigned s_tkey;

    int row = blockIdx.x;
    int tid = threadIdx.x;

    // vector load of bf16 row + key transform (8 keys per uint4)
    const uint4* zr4 = (const uint4*)(g_zb + (size_t)row * LATENT);
    for (int i = tid; i < LATENT / 8; i += 256) {
        uint4 v = zr4[i];
        uint32_t w[4] = {v.x, v.y, v.z, v.w};
#pragma unroll
        for (int j = 0; j < 4; j++) {
            uint32_t lo = f2k16(w[j] & 0xFFFFu);
            uint32_t hi = f2k16(w[j] >> 16);
            w[j] = lo | (hi << 16);
        }
        ((uint4*)keys)[i] = make_uint4(w[0], w[1], w[2], w[3]);
    }
    for (int i = tid; i < IN_DIM; i += 256)
        xrow[i] = x[(size_t)row * IN_DIM + i];
    if (tid == 0) { s_need = KSEL; s_cnt = 0; s_nnz = 0; s_tkey = 0xFFFFFFFFu; }

    // pass 1: high byte
    hist[tid] = 0;
    __syncthreads();
    for (int i = tid; i < LATENT; i += 256)
        atomicAdd(&hist[keys[i] >> 8], 1u);
    __syncthreads();
    if (tid == 0) {
        int need = s_need;
        int b = 255;
        for (; b > 0; b--) {
            int c = (int)hist[b];
            if (c >= need) break;
            need -= c;
        }
        s_bin = b; s_need = need;
    }
    __syncthreads();
    unsigned b1 = (unsigned)s_bin;

    // pass 2: low byte among matching high byte
    hist[tid] = 0;
    __syncthreads();
    for (int i = tid; i < LATENT; i += 256) {
        unsigned k = keys[i];
        if ((k >> 8) == b1) atomicAdd(&hist[k & 0xFFu], 1u);
    }
    __syncthreads();
    if (tid == 0) {
        int need = s_need;
        int b = 255;
        for (; b > 0; b--) {
            int c = (int)hist[b];
            if (c >= need) break;
            need -= c;
        }
        s_bin = b;
    }
    __syncthreads();
    unsigned prefix16 = (b1 << 8) | (unsigned)s_bin;

    // collect candidates above margin cut (approx 32nd-largest minus margin)
    float cut = k2f16(prefix16) - MARGIN;
    for (int i = tid; i < LATENT; i += 256) {
        if (k2f16(keys[i]) > cut) {
            int p = atomicAdd(&s_cnt, 1);
            if (p < MAXCAND) cidx[p] = i;
        }
    }
    __syncthreads();
    int ncand = min(s_cnt, MAXCAND);

    // exact fp32 recompute of candidates (warp per candidate)
    int wid = tid >> 5, lane = tid & 31;
    for (int c = wid; c < ncand; c += 8) {
        const float* wr = enc_w + (size_t)cidx[c] * IN_DIM;
        float p = 0.0f;
        for (int j = lane; j < IN_DIM; j += 32) p += xrow[j] * wr[j];
#pragma unroll
        for (int o = 16; o; o >>= 1) p += __shfl_xor_sync(0xFFFFFFFFu, p, o);
        if (lane == 0) cval[c] = p + enc_b[cidx[c]];
    }
    __syncthreads();

    // exact 32nd largest among candidates
    if (tid < ncand) {
        float v = cval[tid];
        int cg = 0;
        for (int j = 0; j < ncand; j++) cg += (cval[j] > v) ? 1 : 0;
        if (cg <= KSEL - 1) atomicMin(&s_tkey, f2k32(__float_as_uint(v)));
    }
    __syncthreads();
    float thresh = k2f32(s_tkey);

    // zero z_sparse row with float4 stores, then scatter exact entries
    float4* outr4 = (float4*)(zs_out + (size_t)row * LATENT);
    float4 z4 = make_float4(0.f, 0.f, 0.f, 0.f);
    for (int i = tid; i < LATENT / 4; i += 256) outr4[i] = z4;
    __syncthreads();
    float* outr = zs_out + (size_t)row * LATENT;
    if (tid < ncand) {
        float d = cval[tid] - thresh;
        if (d > 0.0f) {
            outr[cidx[tid]] = d;
            int p = atomicAdd(&s_nnz, 1);
            g_sv[(size_t)row * KSEL + p] = d;
            g_si[(size_t)row * KSEL + p] = cidx[tid];
        }
    }
    __syncthreads();
    if (tid == 0) g_nnz[row] = s_nnz;
}

// ---------------- 4) sparse decoder ----------------
__global__ void __launch_bounds__(256) decoder_kernel(
    const float* __restrict__ dec_b, float* __restrict__ xr)
{
    __shared__ float sval[KSEL];
    __shared__ int   sidx[KSEL];
    __shared__ int   snnz;
    int row = blockIdx.x;
    int tid = threadIdx.x;
    if (tid == 0) snnz = g_nnz[row];
    if (tid < KSEL) {
        sval[tid] = g_sv[(size_t)row * KSEL + tid];
        sidx[tid] = g_si[(size_t)row * KSEL + tid];
    }
    __syncthreads();

    int n = snnz;
    int c0 = tid, c1 = tid + 256, c2 = tid + 512;
    float acc0 = 0.f, acc1 = 0.f, acc2 = 0.f;
    for (int j = 0; j < n; j++) {
        float v = sval[j];
        const float* wrow = g_decT + (size_t)sidx[j] * IN_DIM;
        acc0 += v * wrow[c0];
        acc1 += v * wrow[c1];
        acc2 += v * wrow[c2];
    }
    float* o = xr + (size_t)row * IN_DIM;
    o[c0] = acc0 + dec_b[c0];
    o[c1] = acc1 + dec_b[c1];
    o[c2] = acc2 + dec_b[c2];
}

// ---------------- launch ----------------
extern "C" void kernel_launch(void* const* d_in, const int* in_sizes, int n_in,
                              void* d_out, int out_size) {
    const float* x     = (const float*)d_in[0];
    const float* enc_w = (const float*)d_in[1];
    const float* enc_b = (const float*)d_in[2];
    const float* dec_w = (const float*)d_in[3];
    const float* dec_b = (const float*)d_in[4];

    float* out      = (float*)d_out;
    float* x_recon  = out;
    float* z_sparse = out + (size_t)BATCH * IN_DIM;

    __nv_bfloat16 *xb, *wb;
    cudaGetSymbolAddress((void**)&xb, g_xb);
    cudaGetSymbolAddress((void**)&wb, g_wb);

    int nx4 = BATCH * IN_DIM / 4;
    int nw4 = LATENT * IN_DIM / 4;
    convert_bf16_kernel<<<(nx4 + 255) / 256, 256>>>(x, xb, nx4);
    convert_bf16_kernel<<<(nw4 + 255) / 256, 256>>>(enc_w, wb, nw4);

    transpose_dec_kernel<<<dim3(LATENT / 32, IN_DIM / 32), dim3(32, 8)>>>(dec_w);

    const int gemm_smem = 3 * STAGE_BYTES;  // 98304
    cudaFuncSetAttribute(encoder_hmma_kernel,
                         cudaFuncAttributeMaxDynamicSharedMemorySize, gemm_smem);
    encoder_hmma_kernel<<<dim3(LATENT / BN, BATCH / BM), 256, gemm_smem>>>(enc_b);

    const int topk_smem = LATENT * 2 + 256 * 4 + IN_DIM * 4 + MAXCAND * 8;
    cudaFuncSetAttribute(topk_kernel, cudaFuncAttributeMaxDynamicSharedMemorySize, topk_smem);
    topk_kernel<<<BATCH, 256, topk_smem>>>(x, enc_w, enc_b, z_sparse);

    decoder_kernel<<<BATCH, 256>>>(dec_b, x_recon);
}